// round 3
// baseline (speedup 1.0000x reference)
#include <cuda_runtime.h>
#include <cstdint>

#define B_  4
#define T_  2048
#define H_  16
#define DK_ 64
#define D_  1024
#define LDP 68   // padded row stride (floats) for attention smem tiles; 68*4B keeps float4 alignment, rotates banks

// Scratch (device globals — allocation-free per harness rules)
__device__ float g_Q[(size_t)B_*H_*T_*DK_];
__device__ float g_K[(size_t)B_*H_*T_*DK_];
__device__ float g_V[(size_t)B_*H_*T_*DK_];
__device__ float g_A[(size_t)B_*T_*D_];

// ---------------------------------------------------------------------------
// 128x128x8 fp32 SIMT GEMM:  C[M,N] = A[M,K] @ W[K,N] + bias[N]
// qkv_scatter=1: N=3072 output is scattered into head-major Q/K/V buffers.
// ---------------------------------------------------------------------------
__global__ __launch_bounds__(256) void sgemm128(
    const float* __restrict__ A, const float* __restrict__ W,
    const float* __restrict__ bias,
    float* __restrict__ C0, float* __restrict__ C1, float* __restrict__ C2,
    int M, int N, int K, int qkv_scatter)
{
    __shared__ float As[8][132];   // A tile transposed [k][m], pad 4 -> conflict-free transpose store
    __shared__ float Bs[8][128];   // W tile [k][n]

    const int tid = threadIdx.x;
    const int ty = tid >> 4, tx = tid & 15;
    const int m0 = blockIdx.y * 128, n0 = blockIdx.x * 128;

    float acc[8][8];
#pragma unroll
    for (int i = 0; i < 8; i++)
#pragma unroll
        for (int j = 0; j < 8; j++) acc[i][j] = 0.f;

    const int arow = tid >> 1;          // 0..127
    const int acol = (tid & 1) * 4;     // 0 or 4
    const int brow = tid >> 5;          // 0..7
    const int bcol = (tid & 31) * 4;    // 0..124

    const float* Ap = A + (size_t)(m0 + arow) * K + acol;
    const float* Bp = W + (size_t)brow * N + n0 + bcol;

    for (int k0 = 0; k0 < K; k0 += 8) {
        float4 av = *(const float4*)(Ap + k0);
        float4 bv = *(const float4*)(Bp + (size_t)k0 * N);
        As[acol + 0][arow] = av.x;
        As[acol + 1][arow] = av.y;
        As[acol + 2][arow] = av.z;
        As[acol + 3][arow] = av.w;
        *(float4*)&Bs[brow][bcol] = bv;
        __syncthreads();

#pragma unroll
        for (int kk = 0; kk < 8; kk++) {
            float af[8], bf[8];
            *(float4*)(af)     = *(const float4*)&As[kk][ty * 8];
            *(float4*)(af + 4) = *(const float4*)&As[kk][ty * 8 + 4];
            *(float4*)(bf)     = *(const float4*)&Bs[kk][tx * 8];
            *(float4*)(bf + 4) = *(const float4*)&Bs[kk][tx * 8 + 4];
#pragma unroll
            for (int i = 0; i < 8; i++)
#pragma unroll
                for (int j = 0; j < 8; j++)
                    acc[i][j] = fmaf(af[i], bf[j], acc[i][j]);
        }
        __syncthreads();
    }

#pragma unroll
    for (int i = 0; i < 8; i++) {
        const int m = m0 + ty * 8 + i;
        const int b = m >> 11;          // m / 2048
        const int t = m & 2047;
#pragma unroll
        for (int j = 0; j < 8; j++) {
            const int n = n0 + tx * 8 + j;
            const float v = acc[i][j] + bias[n];
            if (!qkv_scatter) {
                C0[(size_t)m * N + n] = v;
            } else {
                const int part = n >> 10;       // 0=Q 1=K 2=V
                const int d    = n & 1023;
                const int h    = d >> 6;
                const int dk   = d & 63;
                float* dst = (part == 0) ? C0 : ((part == 1) ? C1 : C2);
                dst[(((size_t)(b * H_ + h)) * T_ + t) * DK_ + dk] = v;
            }
        }
    }
}

// ---------------------------------------------------------------------------
// Flash attention (causal, online softmax), fp32.
// One block = (b, h, 64-query tile). Block 256 threads, each owns 4x4 of a
// 64x64 S/P tile and 4x4 of the 64x64 O tile.
// ---------------------------------------------------------------------------
__global__ __launch_bounds__(256) void flash_attn_kernel(
    const float* __restrict__ Q, const float* __restrict__ K,
    const float* __restrict__ V, float* __restrict__ O)
{
    extern __shared__ float sm[];
    float* qs   = sm;                 // [64][LDP]  Q tile [row][d]
    float* bs   = sm + 64 * LDP;      // [64][LDP]  K^T tile [d][key], later V tile [key][d]
    float* ss   = sm + 2 * 64 * LDP;  // [64][LDP]  S / P tile [row][key]
    float* m_s  = sm + 3 * 64 * LDP;  // [64] running rowmax
    float* l_s  = m_s + 64;           // [64] running rowsum
    float* al_s = m_s + 128;          // [64] exp(m_old - m_new)

    const int tid = threadIdx.x;
    const int ty = tid >> 4, tx = tid & 15;
    const int r0 = ty * 4, c0 = tx * 4;
    const int q0 = blockIdx.x * 64;
    const int h = blockIdx.y, b = blockIdx.z;
    const size_t hbase = ((size_t)(b * H_ + h)) * T_ * DK_;

    // Load Q tile (vectorized, coalesced)
#pragma unroll
    for (int it = 0; it < 4; it++) {
        int i4 = tid + 256 * it;
        int r = i4 >> 4, c = (i4 & 15) * 4;
        *(float4*)&qs[r * LDP + c] =
            *(const float4*)&Q[hbase + (size_t)(q0 + r) * DK_ + c];
    }
    if (tid < 64) { m_s[tid] = -1e30f; l_s[tid] = 0.f; }

    float o[16];
#pragma unroll
    for (int i = 0; i < 16; i++) o[i] = 0.f;

    for (int k0 = 0; k0 <= q0; k0 += 64) {
        __syncthreads();   // prev iter's PV done before overwriting bs/ss; Q/init visible on first iter

        // Load K^T tile: bs[d][key] = K[key][d]
#pragma unroll
        for (int it = 0; it < 16; it++) {
            int i = tid + 256 * it;
            int r = i >> 6, d = i & 63;
            bs[d * LDP + r] = K[hbase + (size_t)(k0 + r) * DK_ + d];
        }
        __syncthreads();

        // S = Q @ K^T
        float s[16];
#pragma unroll
        for (int i = 0; i < 16; i++) s[i] = 0.f;
#pragma unroll
        for (int d4 = 0; d4 < 16; d4++) {
            float qv[16];
#pragma unroll
            for (int i = 0; i < 4; i++) {
                float4 t = *(const float4*)&qs[(r0 + i) * LDP + d4 * 4];
                qv[i * 4 + 0] = t.x; qv[i * 4 + 1] = t.y;
                qv[i * 4 + 2] = t.z; qv[i * 4 + 3] = t.w;
            }
#pragma unroll
            for (int u = 0; u < 4; u++) {
                float4 t = *(const float4*)&bs[(d4 * 4 + u) * LDP + c0];
                float k0v = t.x, k1v = t.y, k2v = t.z, k3v = t.w;
#pragma unroll
                for (int i = 0; i < 4; i++) {
                    s[i * 4 + 0] = fmaf(qv[i * 4 + u], k0v, s[i * 4 + 0]);
                    s[i * 4 + 1] = fmaf(qv[i * 4 + u], k1v, s[i * 4 + 1]);
                    s[i * 4 + 2] = fmaf(qv[i * 4 + u], k2v, s[i * 4 + 2]);
                    s[i * 4 + 3] = fmaf(qv[i * 4 + u], k3v, s[i * 4 + 3]);
                }
            }
        }
        // scale + causal mask + store S
#pragma unroll
        for (int i = 0; i < 4; i++) {
            const int qi = q0 + r0 + i;
#pragma unroll
            for (int j = 0; j < 4; j++) {
                const int kj = k0 + c0 + j;
                float v = s[i * 4 + j] * 0.125f;  // 1/sqrt(64)
                if (kj > qi) v = -1e30f;
                ss[(r0 + i) * LDP + c0 + j] = v;
            }
        }
        __syncthreads();

        // Load V tile into bs (K no longer needed); tid<64 compute row stats
#pragma unroll
        for (int it = 0; it < 4; it++) {
            int i4 = tid + 256 * it;
            int r = i4 >> 4, c = (i4 & 15) * 4;
            *(float4*)&bs[r * LDP + c] =
                *(const float4*)&V[hbase + (size_t)(k0 + r) * DK_ + c];
        }
        if (tid < 64) {
            float mold = m_s[tid], mx = mold;
            for (int c = 0; c < 64; c++) mx = fmaxf(mx, ss[tid * LDP + c]);
            al_s[tid] = __expf(mold - mx);
            m_s[tid] = mx;
        }
        __syncthreads();

        // P = exp(S - m_new); rescale O accumulators
#pragma unroll
        for (int i = 0; i < 4; i++) {
            const float mn = m_s[r0 + i];
            const float al = al_s[r0 + i];
#pragma unroll
            for (int j = 0; j < 4; j++) {
                const int idx = (r0 + i) * LDP + c0 + j;
                ss[idx] = __expf(ss[idx] - mn);
                o[i * 4 + j] *= al;
            }
        }
        __syncthreads();

        // rowsum update (tid<64) + O += P @ V (all threads)
        if (tid < 64) {
            float sum = 0.f;
            for (int c = 0; c < 64; c++) sum += ss[tid * LDP + c];
            l_s[tid] = l_s[tid] * al_s[tid] + sum;
        }
#pragma unroll
        for (int k4 = 0; k4 < 16; k4++) {
            float pv[16];
#pragma unroll
            for (int i = 0; i < 4; i++) {
                float4 t = *(const float4*)&ss[(r0 + i) * LDP + k4 * 4];
                pv[i * 4 + 0] = t.x; pv[i * 4 + 1] = t.y;
                pv[i * 4 + 2] = t.z; pv[i * 4 + 3] = t.w;
            }
#pragma unroll
            for (int u = 0; u < 4; u++) {
                float4 t = *(const float4*)&bs[(k4 * 4 + u) * LDP + c0];
                float v0 = t.x, v1 = t.y, v2 = t.z, v3 = t.w;
#pragma unroll
                for (int i = 0; i < 4; i++) {
                    o[i * 4 + 0] = fmaf(pv[i * 4 + u], v0, o[i * 4 + 0]);
                    o[i * 4 + 1] = fmaf(pv[i * 4 + u], v1, o[i * 4 + 1]);
                    o[i * 4 + 2] = fmaf(pv[i * 4 + u], v2, o[i * 4 + 2]);
                    o[i * 4 + 3] = fmaf(pv[i * 4 + u], v3, o[i * 4 + 3]);
                }
            }
        }
    }
    __syncthreads();   // l_s final

    // Normalize and write [B,T,D] with head offset
#pragma unroll
    for (int i = 0; i < 4; i++) {
        const float inv = 1.f / l_s[r0 + i];
        const int t = q0 + r0 + i;
#pragma unroll
        for (int j = 0; j < 4; j++) {
            O[((size_t)(b * T_ + t)) * D_ + h * DK_ + c0 + j] = o[i * 4 + j] * inv;
        }
    }
}

// ---------------------------------------------------------------------------
extern "C" void kernel_launch(void* const* d_in, const int* in_sizes, int n_in,
                              void* d_out, int out_size)
{
    const float* x     = (const float*)d_in[0];
    const float* W_qkv = (const float*)d_in[1];
    const float* b_qkv = (const float*)d_in[2];
    const float* W_o   = (const float*)d_in[3];
    const float* b_o   = (const float*)d_in[4];

    float *Qp, *Kp, *Vp, *Ap;
    cudaGetSymbolAddress((void**)&Qp, g_Q);
    cudaGetSymbolAddress((void**)&Kp, g_K);
    cudaGetSymbolAddress((void**)&Vp, g_V);
    cudaGetSymbolAddress((void**)&Ap, g_A);

    // 1) QKV projection + head scatter: [8192,1024] @ [1024,3072]
    {
        dim3 grid(3 * D_ / 128, (B_ * T_) / 128);
        sgemm128<<<grid, 256>>>(x, W_qkv, b_qkv, Qp, Kp, Vp,
                                B_ * T_, 3 * D_, D_, 1);
    }

    // 2) Causal flash attention
    {
        const int smem_bytes = (3 * 64 * LDP + 3 * 64) * (int)sizeof(float); // 52992
        cudaFuncSetAttribute(flash_attn_kernel,
                             cudaFuncAttributeMaxDynamicSharedMemorySize,
                             smem_bytes);
        dim3 grid(T_ / 64, H_, B_);
        flash_attn_kernel<<<grid, 256, smem_bytes>>>(Qp, Kp, Vp, Ap);
    }

    // 3) Output projection: [8192,1024] @ [1024,1024] -> d_out
    {
        dim3 grid(D_ / 128, (B_ * T_) / 128);
        sgemm128<<<grid, 256>>>(Ap, W_o, b_o, (float*)d_out, nullptr, nullptr,
                                B_ * T_, D_, D_, 0);
    }
}

// round 5
// speedup vs baseline: 1.5693x; 1.5693x over previous
#include <cuda_runtime.h>
#include <cuda_bf16.h>
#include <cstdint>

#define B_  4
#define T_  2048
#define H_  16
#define DK_ 64
#define D_  1024
#define GK  1024
#define LDP 68

// ---------------- scratch (device globals; allocation-free) ----------------
__device__ __align__(16) float g_Q[(size_t)B_*H_*T_*DK_];
__device__ __align__(16) float g_K[(size_t)B_*H_*T_*DK_];
__device__ __align__(16) float g_V[(size_t)B_*H_*T_*DK_];
__device__ __align__(16) float g_A[(size_t)B_*T_*D_];
__device__ __align__(16) __nv_bfloat16 g_Xh[(size_t)B_*T_*D_];
__device__ __align__(16) __nv_bfloat16 g_Xl[(size_t)B_*T_*D_];
__device__ __align__(16) __nv_bfloat16 g_Ah[(size_t)B_*T_*D_];
__device__ __align__(16) __nv_bfloat16 g_Al[(size_t)B_*T_*D_];
__device__ __align__(16) __nv_bfloat16 g_Wqh[(size_t)3*D_*D_];   // [N=3072][K=1024] K-major
__device__ __align__(16) __nv_bfloat16 g_Wql[(size_t)3*D_*D_];
__device__ __align__(16) __nv_bfloat16 g_Woh[(size_t)D_*D_];     // [N=1024][K=1024]
__device__ __align__(16) __nv_bfloat16 g_Wol[(size_t)D_*D_];

// ---------------- helpers ----------------
__device__ __forceinline__ uint32_t smem_u32(const void* p) {
    uint32_t a;
    asm("{ .reg .u64 t; cvta.to.shared.u64 t, %1; cvt.u32.u64 %0, t; }" : "=r"(a) : "l"(p));
    return a;
}
#define SWZ128(o) ((o) ^ (((o) >> 3) & 0x70))

#define LDMX4(r0, r1, r2, r3, addr)                                           \
    asm volatile("ldmatrix.sync.aligned.m8n8.x4.shared.b16 {%0,%1,%2,%3}, [%4];" \
                 : "=r"(r0), "=r"(r1), "=r"(r2), "=r"(r3) : "r"(addr))

#define MMA16816(d, a, b0v, b1v)                                              \
    asm volatile("mma.sync.aligned.m16n8k16.row.col.f32.bf16.bf16.f32 "       \
                 "{%0,%1,%2,%3}, {%4,%5,%6,%7}, {%8,%9}, {%0,%1,%2,%3};"      \
                 : "+f"((d)[0]), "+f"((d)[1]), "+f"((d)[2]), "+f"((d)[3])     \
                 : "r"((a)[0]), "r"((a)[1]), "r"((a)[2]), "r"((a)[3]),        \
                   "r"(b0v), "r"(b1v))

// ---------------- prep: fp32 -> bf16 hi/lo split ----------------
__global__ __launch_bounds__(256) void split_bf16(const float* __restrict__ in,
                                                  __nv_bfloat16* __restrict__ hi,
                                                  __nv_bfloat16* __restrict__ lo, int n4) {
    int i = blockIdx.x * 256 + threadIdx.x;
    if (i >= n4) return;
    float4 v = ((const float4*)in)[i];
    union { __nv_bfloat16 b[4]; uint2 u; } H, L;
    const float* f = &v.x;
#pragma unroll
    for (int k = 0; k < 4; k++) {
        __nv_bfloat16 h = __float2bfloat16(f[k]);
        H.b[k] = h;
        L.b[k] = __float2bfloat16(f[k] - __bfloat162float(h));
    }
    ((uint2*)hi)[i] = H.u;
    ((uint2*)lo)[i] = L.u;
}

// ---------------- prep: W[K,N] -> Wt[N,K] bf16 hi/lo ----------------
__global__ __launch_bounds__(256) void transpose_split(const float* __restrict__ W,
                                                       __nv_bfloat16* __restrict__ Th,
                                                       __nv_bfloat16* __restrict__ Tl, int N) {
    __shared__ float tile[32][33];
    const int n0 = blockIdx.x * 32, k0 = blockIdx.y * 32;
    const int tx = threadIdx.x, ty = threadIdx.y;   // 32 x 8
#pragma unroll
    for (int i = 0; i < 4; i++)
        tile[ty + 8 * i][tx] = W[(size_t)(k0 + ty + 8 * i) * N + n0 + tx];
    __syncthreads();
#pragma unroll
    for (int i = 0; i < 4; i++) {
        float v = tile[tx][ty + 8 * i];
        __nv_bfloat16 h = __float2bfloat16(v);
        size_t o = (size_t)(n0 + ty + 8 * i) * GK + k0 + tx;
        Th[o] = h;
        Tl[o] = __float2bfloat16(v - __bfloat162float(h));
    }
}

// ---------------- mma.sync bf16 GEMM: C[M,N] = (Ah+Al)@(Bh+Bl)^T + bias -----
// A*: [M,1024] bf16 K-major.  B*: [N,1024] bf16 K-major.  3-term split.
// Block: 256 thr (8 warps, 2x4), tile 128x128, K chunk 64, SW128 smem swizzle.
#define TILE_BYTES 16384   // 128 rows x 128 bytes (64 bf16)
__global__ __launch_bounds__(256) void gemm_mma(
    const __nv_bfloat16* __restrict__ Ah, const __nv_bfloat16* __restrict__ Al,
    const __nv_bfloat16* __restrict__ Bh, const __nv_bfloat16* __restrict__ Bl,
    const float* __restrict__ bias,
    float* __restrict__ C0, float* __restrict__ C1, float* __restrict__ C2,
    int N, int qkv_scatter)
{
    extern __shared__ char smem[];
    const uint32_t sb = smem_u32(smem);
    const uint32_t sAh = sb, sAl = sb + TILE_BYTES,
                   sBh = sb + 2 * TILE_BYTES, sBl = sb + 3 * TILE_BYTES;
    char* pAh = smem;           char* pAl = smem + TILE_BYTES;
    char* pBh = smem + 2 * TILE_BYTES; char* pBl = smem + 3 * TILE_BYTES;

    const int tid = threadIdx.x, lane = tid & 31, wid = tid >> 5;
    const int wm = (wid & 1) * 64;       // warp M offset
    const int wn = (wid >> 1) * 32;      // warp N offset
    const int m0 = blockIdx.y * 128, n0 = blockIdx.x * 128;

    float acc[4][4][4];
#pragma unroll
    for (int i = 0; i < 4; i++)
#pragma unroll
        for (int j = 0; j < 4; j++)
#pragma unroll
            for (int k = 0; k < 4; k++) acc[i][j][k] = 0.f;

    // gmem load indices: r = row in tile, seg = 16B segment along K
    const int lr = tid >> 3, lseg = tid & 7;
    const uint32_t lso = SWZ128((uint32_t)(lr * 128 + lseg * 16));

    // ldmatrix address components
    const int a_row = wm + (lane & 15);
    const int a_k16 = (lane >> 4);              // 0/1: 16B granule
    const int b_row = wn + (lane & 7) + ((lane & 16) >> 1);
    const int b_k16 = (lane >> 3) & 1;

    for (int c = 0; c < 16; c++) {
        __syncthreads();
        const int kb = c * 64;
#pragma unroll
        for (int it = 0; it < 4; it++) {
            const int r = lr + 32 * it;
            const size_t goA = (size_t)(m0 + r) * GK + kb + lseg * 8;
            const size_t goB = (size_t)(n0 + r) * GK + kb + lseg * 8;
            const uint32_t so = SWZ128((uint32_t)(r * 128 + lseg * 16));
            *(uint4*)(pAh + so) = *(const uint4*)(Ah + goA);
            *(uint4*)(pAl + so) = *(const uint4*)(Al + goA);
            *(uint4*)(pBh + so) = *(const uint4*)(Bh + goB);
            *(uint4*)(pBl + so) = *(const uint4*)(Bl + goB);
        }
        __syncthreads();

#pragma unroll
        for (int kk = 0; kk < 4; kk++) {
            const uint32_t akoff = kk * 32 + a_k16 * 16;
            const uint32_t bkoff = kk * 32 + b_k16 * 16;
            uint32_t ah[4][4], al[4][4], bh[2][4], bl[2][4];
#pragma unroll
            for (int mi = 0; mi < 4; mi++) {
                const uint32_t off = SWZ128((uint32_t)((a_row + mi * 16) * 128) + akoff);
                LDMX4(ah[mi][0], ah[mi][1], ah[mi][2], ah[mi][3], sAh + off);
                LDMX4(al[mi][0], al[mi][1], al[mi][2], al[mi][3], sAl + off);
            }
#pragma unroll
            for (int nj = 0; nj < 2; nj++) {
                const uint32_t off = SWZ128((uint32_t)((b_row + nj * 16) * 128) + bkoff);
                LDMX4(bh[nj][0], bh[nj][1], bh[nj][2], bh[nj][3], sBh + off);
                LDMX4(bl[nj][0], bl[nj][1], bl[nj][2], bl[nj][3], sBl + off);
            }
#pragma unroll
            for (int mi = 0; mi < 4; mi++)
#pragma unroll
                for (int nj = 0; nj < 2; nj++)
#pragma unroll
                    for (int q = 0; q < 2; q++) {
                        float* d = acc[mi][nj * 2 + q];
                        MMA16816(d, ah[mi], bh[nj][q * 2], bh[nj][q * 2 + 1]);
                        MMA16816(d, al[mi], bh[nj][q * 2], bh[nj][q * 2 + 1]);
                        MMA16816(d, ah[mi], bl[nj][q * 2], bl[nj][q * 2 + 1]);
                    }
        }
    }

    // epilogue: direct register -> gmem with bias
    const int rl = lane >> 2;            // 0..7
    const int cl = (lane & 3) * 2;       // 0,2,4,6
#pragma unroll
    for (int mi = 0; mi < 4; mi++) {
        const int r_base = wm + mi * 16 + rl;
#pragma unroll
        for (int ni = 0; ni < 4; ni++) {
            const int cn = wn + ni * 8 + cl;
            const float2 b2 = *(const float2*)&bias[n0 + cn];
#pragma unroll
            for (int half = 0; half < 2; half++) {
                const int m = m0 + r_base + half * 8;
                float2 v;
                v.x = acc[mi][ni][half * 2 + 0] + b2.x;
                v.y = acc[mi][ni][half * 2 + 1] + b2.y;
                if (!qkv_scatter) {
                    *(float2*)&C0[(size_t)m * N + n0 + cn] = v;
                } else {
                    const int b = m >> 11, t = m & 2047;
                    const int part = n0 >> 10;
                    const int d = (n0 & 1023) + cn;
                    const int h = d >> 6, dk = d & 63;
                    float* dst = (part == 0) ? C0 : ((part == 1) ? C1 : C2);
                    *(float2*)&dst[(((size_t)(b * H_ + h)) * T_ + t) * DK_ + dk] = v;
                }
            }
        }
    }
}

// ---------------- flash attention (unchanged, known-good) ----------------
__global__ __launch_bounds__(256) void flash_attn_kernel(
    const float* __restrict__ Q, const float* __restrict__ K,
    const float* __restrict__ V, float* __restrict__ O)
{
    extern __shared__ float sm[];
    float* qs   = sm;
    float* bs   = sm + 64 * LDP;
    float* ss   = sm + 2 * 64 * LDP;
    float* m_s  = sm + 3 * 64 * LDP;
    float* l_s  = m_s + 64;
    float* al_s = m_s + 128;

    const int tid = threadIdx.x;
    const int ty = tid >> 4, tx = tid & 15;
    const int r0 = ty * 4, c0 = tx * 4;
    const int q0 = blockIdx.x * 64;
    const int h = blockIdx.y, b = blockIdx.z;
    const size_t hbase = ((size_t)(b * H_ + h)) * T_ * DK_;

#pragma unroll
    for (int it = 0; it < 4; it++) {
        int i4 = tid + 256 * it;
        int r = i4 >> 4, c = (i4 & 15) * 4;
        *(float4*)&qs[r * LDP + c] =
            *(const float4*)&Q[hbase + (size_t)(q0 + r) * DK_ + c];
    }
    if (tid < 64) { m_s[tid] = -1e30f; l_s[tid] = 0.f; }

    float o[16];
#pragma unroll
    for (int i = 0; i < 16; i++) o[i] = 0.f;

    for (int k0 = 0; k0 <= q0; k0 += 64) {
        __syncthreads();
#pragma unroll
        for (int it = 0; it < 16; it++) {
            int i = tid + 256 * it;
            int r = i >> 6, d = i & 63;
            bs[d * LDP + r] = K[hbase + (size_t)(k0 + r) * DK_ + d];
        }
        __syncthreads();

        float s[16];
#pragma unroll
        for (int i = 0; i < 16; i++) s[i] = 0.f;
#pragma unroll
        for (int d4 = 0; d4 < 16; d4++) {
            float qv[16];
#pragma unroll
            for (int i = 0; i < 4; i++) {
                float4 t = *(const float4*)&qs[(r0 + i) * LDP + d4 * 4];
                qv[i * 4 + 0] = t.x; qv[i * 4 + 1] = t.y;
                qv[i * 4 + 2] = t.z; qv[i * 4 + 3] = t.w;
            }
#pragma unroll
            for (int u = 0; u < 4; u++) {
                float4 t = *(const float4*)&bs[(d4 * 4 + u) * LDP + c0];
                float k0v = t.x, k1v = t.y, k2v = t.z, k3v = t.w;
#pragma unroll
                for (int i = 0; i < 4; i++) {
                    s[i * 4 + 0] = fmaf(qv[i * 4 + u], k0v, s[i * 4 + 0]);
                    s[i * 4 + 1] = fmaf(qv[i * 4 + u], k1v, s[i * 4 + 1]);
                    s[i * 4 + 2] = fmaf(qv[i * 4 + u], k2v, s[i * 4 + 2]);
                    s[i * 4 + 3] = fmaf(qv[i * 4 + u], k3v, s[i * 4 + 3]);
                }
            }
        }
#pragma unroll
        for (int i = 0; i < 4; i++) {
            const int qi = q0 + r0 + i;
#pragma unroll
            for (int j = 0; j < 4; j++) {
                const int kj = k0 + c0 + j;
                float v = s[i * 4 + j] * 0.125f;
                if (kj > qi) v = -1e30f;
                ss[(r0 + i) * LDP + c0 + j] = v;
            }
        }
        __syncthreads();

#pragma unroll
        for (int it = 0; it < 4; it++) {
            int i4 = tid + 256 * it;
            int r = i4 >> 4, c = (i4 & 15) * 4;
            *(float4*)&bs[r * LDP + c] =
                *(const float4*)&V[hbase + (size_t)(k0 + r) * DK_ + c];
        }
        if (tid < 64) {
            float mold = m_s[tid], mx = mold;
            for (int c = 0; c < 64; c++) mx = fmaxf(mx, ss[tid * LDP + c]);
            al_s[tid] = __expf(mold - mx);
            m_s[tid] = mx;
        }
        __syncthreads();

#pragma unroll
        for (int i = 0; i < 4; i++) {
            const float mn = m_s[r0 + i];
            const float al = al_s[r0 + i];
#pragma unroll
            for (int j = 0; j < 4; j++) {
                const int idx = (r0 + i) * LDP + c0 + j;
                ss[idx] = __expf(ss[idx] - mn);
                o[i * 4 + j] *= al;
            }
        }
        __syncthreads();

        if (tid < 64) {
            float sum = 0.f;
            for (int c = 0; c < 64; c++) sum += ss[tid * LDP + c];
            l_s[tid] = l_s[tid] * al_s[tid] + sum;
        }
#pragma unroll
        for (int k4 = 0; k4 < 16; k4++) {
            float pv[16];
#pragma unroll
            for (int i = 0; i < 4; i++) {
                float4 t = *(const float4*)&ss[(r0 + i) * LDP + k4 * 4];
                pv[i * 4 + 0] = t.x; pv[i * 4 + 1] = t.y;
                pv[i * 4 + 2] = t.z; pv[i * 4 + 3] = t.w;
            }
#pragma unroll
            for (int u = 0; u < 4; u++) {
                float4 t = *(const float4*)&bs[(k4 * 4 + u) * LDP + c0];
                float v0 = t.x, v1 = t.y, v2 = t.z, v3 = t.w;
#pragma unroll
                for (int i = 0; i < 4; i++) {
                    o[i * 4 + 0] = fmaf(pv[i * 4 + u], v0, o[i * 4 + 0]);
                    o[i * 4 + 1] = fmaf(pv[i * 4 + u], v1, o[i * 4 + 1]);
                    o[i * 4 + 2] = fmaf(pv[i * 4 + u], v2, o[i * 4 + 2]);
                    o[i * 4 + 3] = fmaf(pv[i * 4 + u], v3, o[i * 4 + 3]);
                }
            }
        }
    }
    __syncthreads();

#pragma unroll
    for (int i = 0; i < 4; i++) {
        const float inv = 1.f / l_s[r0 + i];
        const int t = q0 + r0 + i;
#pragma unroll
        for (int j = 0; j < 4; j++) {
            O[((size_t)(b * T_ + t)) * D_ + h * DK_ + c0 + j] = o[i * 4 + j] * inv;
        }
    }
}

// ---------------------------------------------------------------------------
extern "C" void kernel_launch(void* const* d_in, const int* in_sizes, int n_in,
                              void* d_out, int out_size)
{
    const float* x     = (const float*)d_in[0];
    const float* W_qkv = (const float*)d_in[1];
    const float* b_qkv = (const float*)d_in[2];
    const float* W_o   = (const float*)d_in[3];
    const float* b_o   = (const float*)d_in[4];

    float *Qp, *Kp, *Vp, *Ap;
    __nv_bfloat16 *Xh, *Xl, *Ahp, *Alp, *Wqh, *Wql, *Woh, *Wol;
    cudaGetSymbolAddress((void**)&Qp, g_Q);
    cudaGetSymbolAddress((void**)&Kp, g_K);
    cudaGetSymbolAddress((void**)&Vp, g_V);
    cudaGetSymbolAddress((void**)&Ap, g_A);
    cudaGetSymbolAddress((void**)&Xh, g_Xh);
    cudaGetSymbolAddress((void**)&Xl, g_Xl);
    cudaGetSymbolAddress((void**)&Ahp, g_Ah);
    cudaGetSymbolAddress((void**)&Alp, g_Al);
    cudaGetSymbolAddress((void**)&Wqh, g_Wqh);
    cudaGetSymbolAddress((void**)&Wql, g_Wql);
    cudaGetSymbolAddress((void**)&Woh, g_Woh);
    cudaGetSymbolAddress((void**)&Wol, g_Wol);

    const int M = B_ * T_;
    const int n4 = M * D_ / 4;
    const int smem_gemm = 4 * TILE_BYTES;   // 64 KB

    split_bf16<<<(n4 + 255) / 256, 256>>>(x, Xh, Xl, n4);
    {
        dim3 g(3 * D_ / 32, D_ / 32), blk(32, 8);
        transpose_split<<<g, blk>>>(W_qkv, Wqh, Wql, 3 * D_);
    }
    {
        dim3 g(D_ / 32, D_ / 32), blk(32, 8);
        transpose_split<<<g, blk>>>(W_o, Woh, Wol, D_);
    }

    cudaFuncSetAttribute(gemm_mma, cudaFuncAttributeMaxDynamicSharedMemorySize, smem_gemm);

    // 1) QKV projection (tensor cores) + head scatter
    {
        dim3 grid(3 * D_ / 128, M / 128);
        gemm_mma<<<grid, 256, smem_gemm>>>(Xh, Xl, Wqh, Wql, b_qkv, Qp, Kp, Vp, 3 * D_, 1);
    }

    // 2) causal flash attention (fp32 SIMT)
    {
        const int smem_bytes = (3 * 64 * LDP + 3 * 64) * (int)sizeof(float);
        cudaFuncSetAttribute(flash_attn_kernel,
                             cudaFuncAttributeMaxDynamicSharedMemorySize, smem_bytes);
        dim3 grid(T_ / 64, H_, B_);
        flash_attn_kernel<<<grid, 256, smem_bytes>>>(Qp, Kp, Vp, Ap);
    }

    // 3) output projection (tensor cores)
    split_bf16<<<(n4 + 255) / 256, 256>>>(Ap, Ahp, Alp, n4);
    {
        dim3 grid(D_ / 128, M / 128);
        gemm_mma<<<grid, 256, smem_gemm>>>(Ahp, Alp, Woh, Wol, b_o, (float*)d_out,
                                           nullptr, nullptr, D_, 0);
    }
}

// round 6
// speedup vs baseline: 3.1421x; 2.0022x over previous
#include <cuda_runtime.h>
#include <cuda_bf16.h>
#include <cstdint>

#define B_  4
#define T_  2048
#define H_  16
#define DK_ 64
#define D_  1024
#define GK  1024

// ---------------- scratch (device globals; allocation-free) ----------------
__device__ __align__(16) __nv_bfloat16 g_Qh[(size_t)B_*H_*T_*DK_];
__device__ __align__(16) __nv_bfloat16 g_Ql[(size_t)B_*H_*T_*DK_];
__device__ __align__(16) __nv_bfloat16 g_Kh[(size_t)B_*H_*T_*DK_];
__device__ __align__(16) __nv_bfloat16 g_Kl[(size_t)B_*H_*T_*DK_];
__device__ __align__(16) __nv_bfloat16 g_Vh[(size_t)B_*H_*T_*DK_];
__device__ __align__(16) __nv_bfloat16 g_Vl[(size_t)B_*H_*T_*DK_];
__device__ __align__(16) __nv_bfloat16 g_Xh[(size_t)B_*T_*D_];
__device__ __align__(16) __nv_bfloat16 g_Xl[(size_t)B_*T_*D_];
__device__ __align__(16) __nv_bfloat16 g_Ah[(size_t)B_*T_*D_];
__device__ __align__(16) __nv_bfloat16 g_Al[(size_t)B_*T_*D_];
__device__ __align__(16) __nv_bfloat16 g_Wqh[(size_t)3*D_*D_];
__device__ __align__(16) __nv_bfloat16 g_Wql[(size_t)3*D_*D_];
__device__ __align__(16) __nv_bfloat16 g_Woh[(size_t)D_*D_];
__device__ __align__(16) __nv_bfloat16 g_Wol[(size_t)D_*D_];

// ---------------- helpers ----------------
__device__ __forceinline__ uint32_t smem_u32(const void* p) {
    uint32_t a;
    asm("{ .reg .u64 t; cvta.to.shared.u64 t, %1; cvt.u32.u64 %0, t; }" : "=r"(a) : "l"(p));
    return a;
}
#define SWZ128(o) ((o) ^ (((o) >> 3) & 0x70))

#define LDMX4(r0, r1, r2, r3, addr)                                           \
    asm volatile("ldmatrix.sync.aligned.m8n8.x4.shared.b16 {%0,%1,%2,%3}, [%4];" \
                 : "=r"(r0), "=r"(r1), "=r"(r2), "=r"(r3) : "r"(addr))
#define LDMX4T(r0, r1, r2, r3, addr)                                          \
    asm volatile("ldmatrix.sync.aligned.m8n8.x4.trans.shared.b16 {%0,%1,%2,%3}, [%4];" \
                 : "=r"(r0), "=r"(r1), "=r"(r2), "=r"(r3) : "r"(addr))

#define MMA16816(d, a, b0v, b1v)                                              \
    asm volatile("mma.sync.aligned.m16n8k16.row.col.f32.bf16.bf16.f32 "       \
                 "{%0,%1,%2,%3}, {%4,%5,%6,%7}, {%8,%9}, {%0,%1,%2,%3};"      \
                 : "+f"((d)[0]), "+f"((d)[1]), "+f"((d)[2]), "+f"((d)[3])     \
                 : "r"((a)[0]), "r"((a)[1]), "r"((a)[2]), "r"((a)[3]),        \
                   "r"(b0v), "r"(b1v))

#define CP16(dst, src)                                                        \
    asm volatile("cp.async.cg.shared.global [%0], [%1], 16;" :: "r"(dst), "l"(src))
#define CP_COMMIT() asm volatile("cp.async.commit_group;" ::: "memory")
#define CP_WAIT(n)  asm volatile("cp.async.wait_group %0;" :: "n"(n) : "memory")

__device__ __forceinline__ uint32_t pack_bf16(float a, float b) {
    __nv_bfloat162 h = __floats2bfloat162_rn(a, b);
    return *(uint32_t*)&h;
}

// ---------------- prep: fp32 -> bf16 hi/lo split ----------------
__global__ __launch_bounds__(256) void split_bf16(const float* __restrict__ in,
                                                  __nv_bfloat16* __restrict__ hi,
                                                  __nv_bfloat16* __restrict__ lo, int n4) {
    int i = blockIdx.x * 256 + threadIdx.x;
    if (i >= n4) return;
    float4 v = ((const float4*)in)[i];
    union { __nv_bfloat16 b[4]; uint2 u; } H, L;
    const float* f = &v.x;
#pragma unroll
    for (int k = 0; k < 4; k++) {
        __nv_bfloat16 h = __float2bfloat16(f[k]);
        H.b[k] = h;
        L.b[k] = __float2bfloat16(f[k] - __bfloat162float(h));
    }
    ((uint2*)hi)[i] = H.u;
    ((uint2*)lo)[i] = L.u;
}

// ---------------- prep: W[K,N] -> Wt[N,K] bf16 hi/lo ----------------
__global__ __launch_bounds__(256) void transpose_split(const float* __restrict__ W,
                                                       __nv_bfloat16* __restrict__ Th,
                                                       __nv_bfloat16* __restrict__ Tl, int N) {
    __shared__ float tile[32][33];
    const int n0 = blockIdx.x * 32, k0 = blockIdx.y * 32;
    const int tx = threadIdx.x, ty = threadIdx.y;
#pragma unroll
    for (int i = 0; i < 4; i++)
        tile[ty + 8 * i][tx] = W[(size_t)(k0 + ty + 8 * i) * N + n0 + tx];
    __syncthreads();
#pragma unroll
    for (int i = 0; i < 4; i++) {
        float v = tile[tx][ty + 8 * i];
        __nv_bfloat16 h = __float2bfloat16(v);
        size_t o = (size_t)(n0 + ty + 8 * i) * GK + k0 + tx;
        Th[o] = h;
        Tl[o] = __float2bfloat16(v - __bfloat162float(h));
    }
}

// ---------------- pipelined mma GEMM: C = (Ah+Al)@(Bh+Bl)^T + bias ----------
// mode 0: fp32 out C0[M][N].  mode 1: bf16 hi/lo scatter into Q/K/V buffers.
#define TILE_B 16384
#define STG_B  65536   // 4 tiles per stage
__global__ __launch_bounds__(256) void gemm_mma(
    const __nv_bfloat16* __restrict__ Ah, const __nv_bfloat16* __restrict__ Al,
    const __nv_bfloat16* __restrict__ Bh, const __nv_bfloat16* __restrict__ Bl,
    const float* __restrict__ bias, float* __restrict__ Cf,
    __nv_bfloat16* __restrict__ oQh, __nv_bfloat16* __restrict__ oQl,
    __nv_bfloat16* __restrict__ oKh, __nv_bfloat16* __restrict__ oKl,
    __nv_bfloat16* __restrict__ oVh, __nv_bfloat16* __restrict__ oVl,
    int N, int mode)
{
    extern __shared__ char smem[];
    const uint32_t sb = smem_u32(smem);
    const int tid = threadIdx.x, lane = tid & 31, wid = tid >> 5;
    const int wm = (wid & 1) * 64, wn = (wid >> 1) * 32;
    const int m0 = blockIdx.y * 128, n0 = blockIdx.x * 128;

    float acc[4][4][4];
#pragma unroll
    for (int i = 0; i < 4; i++)
#pragma unroll
        for (int j = 0; j < 4; j++)
#pragma unroll
            for (int k = 0; k < 4; k++) acc[i][j][k] = 0.f;

    const int lr = tid >> 3, lseg = tid & 7;
    const int a_row = wm + (lane & 15), a_k16 = lane >> 4;
    const int b_row = wn + (lane & 7) + ((lane & 16) >> 1), b_k16 = (lane >> 3) & 1;

    // issue loads of chunk c into stage st
    auto issue = [&](int c, int st) {
        const int kb = c * 64;
        const uint32_t stb = sb + st * STG_B;
#pragma unroll
        for (int it = 0; it < 4; it++) {
            const int r = lr + 32 * it;
            const size_t goA = (size_t)(m0 + r) * GK + kb + lseg * 8;
            const size_t goB = (size_t)(n0 + r) * GK + kb + lseg * 8;
            const uint32_t so = SWZ128((uint32_t)(r * 128 + lseg * 16));
            CP16(stb + so, Ah + goA);
            CP16(stb + TILE_B + so, Al + goA);
            CP16(stb + 2 * TILE_B + so, Bh + goB);
            CP16(stb + 3 * TILE_B + so, Bl + goB);
        }
        CP_COMMIT();
    };

    issue(0, 0);
    for (int c = 0; c < 16; c++) {
        if (c + 1 < 16) { issue(c + 1, (c + 1) & 1); CP_WAIT(1); }
        else            { CP_WAIT(0); }
        __syncthreads();
        const uint32_t stb = sb + (c & 1) * STG_B;
        const uint32_t sAh = stb, sAl = stb + TILE_B,
                       sBh = stb + 2 * TILE_B, sBl = stb + 3 * TILE_B;
#pragma unroll
        for (int kk = 0; kk < 4; kk++) {
            const uint32_t akoff = kk * 32 + a_k16 * 16;
            const uint32_t bkoff = kk * 32 + b_k16 * 16;
            uint32_t ah[4][4], al[4][4], bh[2][4], bl[2][4];
#pragma unroll
            for (int mi = 0; mi < 4; mi++) {
                const uint32_t off = SWZ128((uint32_t)((a_row + mi * 16) * 128) + akoff);
                LDMX4(ah[mi][0], ah[mi][1], ah[mi][2], ah[mi][3], sAh + off);
                LDMX4(al[mi][0], al[mi][1], al[mi][2], al[mi][3], sAl + off);
            }
#pragma unroll
            for (int nj = 0; nj < 2; nj++) {
                const uint32_t off = SWZ128((uint32_t)((b_row + nj * 16) * 128) + bkoff);
                LDMX4(bh[nj][0], bh[nj][1], bh[nj][2], bh[nj][3], sBh + off);
                LDMX4(bl[nj][0], bl[nj][1], bl[nj][2], bl[nj][3], sBl + off);
            }
#pragma unroll
            for (int mi = 0; mi < 4; mi++)
#pragma unroll
                for (int nj = 0; nj < 2; nj++)
#pragma unroll
                    for (int q = 0; q < 2; q++) {
                        float* d = acc[mi][nj * 2 + q];
                        MMA16816(d, ah[mi], bh[nj][q * 2], bh[nj][q * 2 + 1]);
                        MMA16816(d, al[mi], bh[nj][q * 2], bh[nj][q * 2 + 1]);
                        MMA16816(d, ah[mi], bl[nj][q * 2], bl[nj][q * 2 + 1]);
                    }
        }
        __syncthreads();
    }

    // epilogue
    const int rl = lane >> 2, cl = (lane & 3) * 2;
#pragma unroll
    for (int mi = 0; mi < 4; mi++) {
        const int r_base = wm + mi * 16 + rl;
#pragma unroll
        for (int ni = 0; ni < 4; ni++) {
            const int cn = wn + ni * 8 + cl;
            const float2 b2 = *(const float2*)&bias[n0 + cn];
#pragma unroll
            for (int half = 0; half < 2; half++) {
                const int m = m0 + r_base + half * 8;
                float v0 = acc[mi][ni][half * 2 + 0] + b2.x;
                float v1 = acc[mi][ni][half * 2 + 1] + b2.y;
                if (mode == 0) {
                    float2 v; v.x = v0; v.y = v1;
                    *(float2*)&Cf[(size_t)m * N + n0 + cn] = v;
                } else {
                    const int b = m >> 11, t = m & 2047;
                    const int part = n0 >> 10;
                    const int d = (n0 & 1023) + cn;
                    const int h = d >> 6, dk = d & 63;
                    __nv_bfloat16 h0 = __float2bfloat16(v0);
                    __nv_bfloat16 h1 = __float2bfloat16(v1);
                    uint32_t hw = pack_bf16(v0, v1);  // rn pair
                    uint32_t lw = pack_bf16(v0 - __bfloat162float(h0),
                                            v1 - __bfloat162float(h1));
                    (void)hw;
                    uint32_t hp;
                    { __nv_bfloat162 t2v; t2v.x = h0; t2v.y = h1; hp = *(uint32_t*)&t2v; }
                    const size_t off = (((size_t)(b * H_ + h)) * T_ + t) * DK_ + dk;
                    __nv_bfloat16 *dh, *dl;
                    if (part == 0)      { dh = oQh; dl = oQl; }
                    else if (part == 1) { dh = oKh; dl = oKl; }
                    else                { dh = oVh; dl = oVl; }
                    *(uint32_t*)(dh + off) = hp;
                    *(uint32_t*)(dl + off) = lw;
                }
            }
        }
    }
}

// ---------------- mma.sync flash attention (causal), 3-term hi/lo ----------
// block: 256 thr / 8 warps; q-tile 128 (warp w owns rows w*16..+16); k-tile 128.
// smem: Qh Ql Kh Kl Vh Vl, each 128x64 bf16 swizzled (16KB) = 96KB.
#define ASM_QH 0
#define ASM_QL 16384
#define ASM_KH 32768
#define ASM_KL 49152
#define ASM_VH 65536
#define ASM_VL 81920
#define ASM_TOT 98304

__global__ __launch_bounds__(256, 1) void attn_mma(
    const __nv_bfloat16* __restrict__ Qh, const __nv_bfloat16* __restrict__ Ql,
    const __nv_bfloat16* __restrict__ Kh, const __nv_bfloat16* __restrict__ Kl,
    const __nv_bfloat16* __restrict__ Vh, const __nv_bfloat16* __restrict__ Vl,
    __nv_bfloat16* __restrict__ Ah, __nv_bfloat16* __restrict__ Al)
{
    extern __shared__ char smem[];
    const uint32_t sb = smem_u32(smem);
    const int tid = threadIdx.x, lane = tid & 31, wid = tid >> 5;
    const int qt = gridDim.x - 1 - blockIdx.x;   // heavy tiles first
    const int q0 = qt * 128;
    const int h = blockIdx.y, b = blockIdx.z;
    const size_t hb = ((size_t)(b * H_ + h)) * T_ * DK_;

    // load Q tile (hi/lo) into smem
    {
#pragma unroll
        for (int it = 0; it < 4; it++) {
            const int u = tid + 256 * it;
            const int r = u >> 3, seg = u & 7;
            const uint32_t so = SWZ128((uint32_t)(r * 128 + seg * 16));
            const size_t g = hb + (size_t)(q0 + r) * DK_ + seg * 8;
            *(uint4*)(smem + ASM_QH + so) = *(const uint4*)(Qh + g);
            *(uint4*)(smem + ASM_QL + so) = *(const uint4*)(Ql + g);
        }
    }
    __syncthreads();

    // Q fragments (persistent)
    const int a_row = wid * 16 + (lane & 15), a_k16 = lane >> 4;
    uint32_t qfh[4][4], qfl[4][4];
#pragma unroll
    for (int kk = 0; kk < 4; kk++) {
        const uint32_t off = SWZ128((uint32_t)(a_row * 128 + kk * 32 + a_k16 * 16));
        LDMX4(qfh[kk][0], qfh[kk][1], qfh[kk][2], qfh[kk][3], sb + ASM_QH + off);
        LDMX4(qfl[kk][0], qfl[kk][1], qfl[kk][2], qfl[kk][3], sb + ASM_QL + off);
    }

    const int b_row = (lane & 7) + ((lane & 16) >> 1), b_k16 = (lane >> 3) & 1;
    const int vm = lane >> 3, vr = lane & 7;
    const int rr = lane >> 2, t2 = (lane & 3) * 2;

    float o[8][4];
#pragma unroll
    for (int i = 0; i < 8; i++)
#pragma unroll
        for (int j = 0; j < 4; j++) o[i][j] = 0.f;
    float m_r = -1e30f, m_r8 = -1e30f, l_r = 0.f, l_r8 = 0.f;

    for (int k0 = 0; k0 <= q0; k0 += 128) {
        __syncthreads();
#pragma unroll
        for (int it = 0; it < 4; it++) {
            const int u = tid + 256 * it;
            const int r = u >> 3, seg = u & 7;
            const uint32_t so = SWZ128((uint32_t)(r * 128 + seg * 16));
            const size_t g = hb + (size_t)(k0 + r) * DK_ + seg * 8;
            *(uint4*)(smem + ASM_KH + so) = *(const uint4*)(Kh + g);
            *(uint4*)(smem + ASM_KL + so) = *(const uint4*)(Kl + g);
            *(uint4*)(smem + ASM_VH + so) = *(const uint4*)(Vh + g);
            *(uint4*)(smem + ASM_VL + so) = *(const uint4*)(Vl + g);
        }
        __syncthreads();

        // S = Q @ K^T (3-term)
        float s[16][4];
#pragma unroll
        for (int i = 0; i < 16; i++)
#pragma unroll
            for (int j = 0; j < 4; j++) s[i][j] = 0.f;
#pragma unroll
        for (int kk = 0; kk < 4; kk++) {
#pragma unroll
            for (int nn = 0; nn < 8; nn++) {
                const uint32_t off = SWZ128((uint32_t)((nn * 16 + b_row) * 128 + kk * 32 + b_k16 * 16));
                uint32_t kh[4], kl[4];
                LDMX4(kh[0], kh[1], kh[2], kh[3], sb + ASM_KH + off);
                LDMX4(kl[0], kl[1], kl[2], kl[3], sb + ASM_KL + off);
                float* s0 = s[2 * nn];
                float* s1 = s[2 * nn + 1];
                MMA16816(s0, qfh[kk], kh[0], kh[1]);
                MMA16816(s0, qfl[kk], kh[0], kh[1]);
                MMA16816(s0, qfh[kk], kl[0], kl[1]);
                MMA16816(s1, qfh[kk], kh[2], kh[3]);
                MMA16816(s1, qfl[kk], kh[2], kh[3]);
                MMA16816(s1, qfh[kk], kl[2], kl[3]);
            }
        }

        // scale + causal mask (only diagonal tile needs mask)
        const bool diag = (k0 == q0);
        const int qi_r = q0 + wid * 16 + rr;
#pragma unroll
        for (int ni = 0; ni < 16; ni++) {
            const int kc = k0 + ni * 8 + t2;
#pragma unroll
            for (int e = 0; e < 4; e++) {
                float v = s[ni][e] * 0.125f;
                if (diag) {
                    const int kj = kc + (e & 1);
                    const int qi = qi_r + ((e >> 1) << 3);
                    if (kj > qi) v = -1e30f;
                }
                s[ni][e] = v;
            }
        }

        // row max (lane-local + shfl over the 4 lanes sharing a row)
        float rmr = -1e30f, rm8 = -1e30f;
#pragma unroll
        for (int ni = 0; ni < 16; ni++) {
            rmr = fmaxf(rmr, fmaxf(s[ni][0], s[ni][1]));
            rm8 = fmaxf(rm8, fmaxf(s[ni][2], s[ni][3]));
        }
        rmr = fmaxf(rmr, __shfl_xor_sync(0xffffffffu, rmr, 1));
        rmr = fmaxf(rmr, __shfl_xor_sync(0xffffffffu, rmr, 2));
        rm8 = fmaxf(rm8, __shfl_xor_sync(0xffffffffu, rm8, 1));
        rm8 = fmaxf(rm8, __shfl_xor_sync(0xffffffffu, rm8, 2));

        const float mnr = fmaxf(m_r, rmr), mn8 = fmaxf(m_r8, rm8);
        const float ar = __expf(m_r - mnr), a8 = __expf(m_r8 - mn8);
        m_r = mnr; m_r8 = mn8;
        l_r *= ar; l_r8 *= a8;
#pragma unroll
        for (int dn = 0; dn < 8; dn++) {
            o[dn][0] *= ar; o[dn][1] *= ar; o[dn][2] *= a8; o[dn][3] *= a8;
        }

        // P = exp(S-m), packed bf16 hi/lo per 16-key step; O += P@V (3-term)
#pragma unroll
        for (int kk = 0; kk < 8; kk++) {
            float p0 = __expf(s[2 * kk][0] - m_r);
            float p1 = __expf(s[2 * kk][1] - m_r);
            float p2 = __expf(s[2 * kk][2] - m_r8);
            float p3 = __expf(s[2 * kk][3] - m_r8);
            float p4 = __expf(s[2 * kk + 1][0] - m_r);
            float p5 = __expf(s[2 * kk + 1][1] - m_r);
            float p6 = __expf(s[2 * kk + 1][2] - m_r8);
            float p7 = __expf(s[2 * kk + 1][3] - m_r8);
            l_r  += p0 + p1 + p4 + p5;
            l_r8 += p2 + p3 + p6 + p7;

            uint32_t pH[4], pL[4];
            {
                __nv_bfloat16 h0 = __float2bfloat16(p0), h1 = __float2bfloat16(p1);
                __nv_bfloat16 h2 = __float2bfloat16(p2), h3 = __float2bfloat16(p3);
                __nv_bfloat16 h4 = __float2bfloat16(p4), h5 = __float2bfloat16(p5);
                __nv_bfloat16 h6 = __float2bfloat16(p6), h7 = __float2bfloat16(p7);
                __nv_bfloat162 w;
                w.x = h0; w.y = h1; pH[0] = *(uint32_t*)&w;
                w.x = h2; w.y = h3; pH[1] = *(uint32_t*)&w;
                w.x = h4; w.y = h5; pH[2] = *(uint32_t*)&w;
                w.x = h6; w.y = h7; pH[3] = *(uint32_t*)&w;
                pL[0] = pack_bf16(p0 - __bfloat162float(h0), p1 - __bfloat162float(h1));
                pL[1] = pack_bf16(p2 - __bfloat162float(h2), p3 - __bfloat162float(h3));
                pL[2] = pack_bf16(p4 - __bfloat162float(h4), p5 - __bfloat162float(h5));
                pL[3] = pack_bf16(p6 - __bfloat162float(h6), p7 - __bfloat162float(h7));
            }
#pragma unroll
            for (int dp = 0; dp < 4; dp++) {
                const uint32_t off = SWZ128((uint32_t)(
                    (kk * 16 + (vm & 1) * 8 + vr) * 128 + (vm >> 1) * 16 + dp * 32));
                uint32_t vh[4], vl[4];
                LDMX4T(vh[0], vh[1], vh[2], vh[3], sb + ASM_VH + off);
                LDMX4T(vl[0], vl[1], vl[2], vl[3], sb + ASM_VL + off);
                float* o0 = o[2 * dp];
                float* o1 = o[2 * dp + 1];
                MMA16816(o0, pH, vh[0], vh[1]);
                MMA16816(o0, pL, vh[0], vh[1]);
                MMA16816(o0, pH, vl[0], vl[1]);
                MMA16816(o1, pH, vh[2], vh[3]);
                MMA16816(o1, pL, vh[2], vh[3]);
                MMA16816(o1, pH, vl[2], vl[3]);
            }
        }
    }

    // epilogue: reduce l across lane group, normalize, split to bf16 hi/lo
    l_r  += __shfl_xor_sync(0xffffffffu, l_r, 1);
    l_r  += __shfl_xor_sync(0xffffffffu, l_r, 2);
    l_r8 += __shfl_xor_sync(0xffffffffu, l_r8, 1);
    l_r8 += __shfl_xor_sync(0xffffffffu, l_r8, 2);
    const float ir = 1.f / l_r, i8 = 1.f / l_r8;
    const int trow = q0 + wid * 16 + rr;
#pragma unroll
    for (int dn = 0; dn < 8; dn++) {
        float v0 = o[dn][0] * ir, v1 = o[dn][1] * ir;
        float v2 = o[dn][2] * i8, v3 = o[dn][3] * i8;
        const int col = h * DK_ + dn * 8 + t2;
        __nv_bfloat16 h0 = __float2bfloat16(v0), h1 = __float2bfloat16(v1);
        __nv_bfloat16 h2 = __float2bfloat16(v2), h3 = __float2bfloat16(v3);
        __nv_bfloat162 w;
        size_t o1 = ((size_t)(b * T_ + trow)) * D_ + col;
        size_t o2 = ((size_t)(b * T_ + trow + 8)) * D_ + col;
        w.x = h0; w.y = h1; *(uint32_t*)(Ah + o1) = *(uint32_t*)&w;
        w.x = h2; w.y = h3; *(uint32_t*)(Ah + o2) = *(uint32_t*)&w;
        *(uint32_t*)(Al + o1) = pack_bf16(v0 - __bfloat162float(h0), v1 - __bfloat162float(h1));
        *(uint32_t*)(Al + o2) = pack_bf16(v2 - __bfloat162float(h2), v3 - __bfloat162float(h3));
    }
}

// ---------------------------------------------------------------------------
extern "C" void kernel_launch(void* const* d_in, const int* in_sizes, int n_in,
                              void* d_out, int out_size)
{
    const float* x     = (const float*)d_in[0];
    const float* W_qkv = (const float*)d_in[1];
    const float* b_qkv = (const float*)d_in[2];
    const float* W_o   = (const float*)d_in[3];
    const float* b_o   = (const float*)d_in[4];

    __nv_bfloat16 *Qh, *Ql, *Kh, *Kl, *Vh, *Vl, *Xh, *Xl, *Ahp, *Alp, *Wqh, *Wql, *Woh, *Wol;
    cudaGetSymbolAddress((void**)&Qh, g_Qh); cudaGetSymbolAddress((void**)&Ql, g_Ql);
    cudaGetSymbolAddress((void**)&Kh, g_Kh); cudaGetSymbolAddress((void**)&Kl, g_Kl);
    cudaGetSymbolAddress((void**)&Vh, g_Vh); cudaGetSymbolAddress((void**)&Vl, g_Vl);
    cudaGetSymbolAddress((void**)&Xh, g_Xh); cudaGetSymbolAddress((void**)&Xl, g_Xl);
    cudaGetSymbolAddress((void**)&Ahp, g_Ah); cudaGetSymbolAddress((void**)&Alp, g_Al);
    cudaGetSymbolAddress((void**)&Wqh, g_Wqh); cudaGetSymbolAddress((void**)&Wql, g_Wql);
    cudaGetSymbolAddress((void**)&Woh, g_Woh); cudaGetSymbolAddress((void**)&Wol, g_Wol);

    const int M = B_ * T_;
    const int n4 = M * D_ / 4;
    const int smem_gemm = 2 * STG_B;   // 128 KB

    split_bf16<<<(n4 + 255) / 256, 256>>>(x, Xh, Xl, n4);
    {
        dim3 g(3 * D_ / 32, D_ / 32), blk(32, 8);
        transpose_split<<<g, blk>>>(W_qkv, Wqh, Wql, 3 * D_);
    }
    {
        dim3 g(D_ / 32, D_ / 32), blk(32, 8);
        transpose_split<<<g, blk>>>(W_o, Woh, Wol, D_);
    }

    cudaFuncSetAttribute(gemm_mma, cudaFuncAttributeMaxDynamicSharedMemorySize, smem_gemm);
    cudaFuncSetAttribute(attn_mma, cudaFuncAttributeMaxDynamicSharedMemorySize, ASM_TOT);

    // 1) QKV projection -> bf16 hi/lo head-major Q/K/V
    {
        dim3 grid(3 * D_ / 128, M / 128);
        gemm_mma<<<grid, 256, smem_gemm>>>(Xh, Xl, Wqh, Wql, b_qkv, nullptr,
                                           Qh, Ql, Kh, Kl, Vh, Vl, 3 * D_, 1);
    }

    // 2) causal flash attention (tensor cores) -> Ah/Al bf16 hi/lo
    {
        dim3 grid(T_ / 128, H_, B_);
        attn_mma<<<grid, 256, ASM_TOT>>>(Qh, Ql, Kh, Kl, Vh, Vl, Ahp, Alp);
    }

    // 3) output projection -> fp32 d_out
    {
        dim3 grid(D_ / 128, M / 128);
        gemm_mma<<<grid, 256, smem_gemm>>>(Ahp, Alp, Woh, Wol, b_o, (float*)d_out,
                                           nullptr, nullptr, nullptr, nullptr, nullptr, nullptr,
                                           D_, 0);
    }
}

// round 7
// speedup vs baseline: 3.2875x; 1.0463x over previous
#include <cuda_runtime.h>
#include <cuda_bf16.h>
#include <cstdint>

#define B_  4
#define T_  2048
#define H_  16
#define DK_ 64
#define D_  1024
#define GK  1024

// ---------------- scratch (device globals; allocation-free) ----------------
__device__ __align__(16) __nv_bfloat16 g_Qh[(size_t)B_*H_*T_*DK_];
__device__ __align__(16) __nv_bfloat16 g_Ql[(size_t)B_*H_*T_*DK_];
__device__ __align__(16) __nv_bfloat16 g_Kh[(size_t)B_*H_*T_*DK_];
__device__ __align__(16) __nv_bfloat16 g_Kl[(size_t)B_*H_*T_*DK_];
__device__ __align__(16) __nv_bfloat16 g_Vh[(size_t)B_*H_*T_*DK_];
__device__ __align__(16) __nv_bfloat16 g_Vl[(size_t)B_*H_*T_*DK_];
__device__ __align__(16) __nv_bfloat16 g_Xh[(size_t)B_*T_*D_];
__device__ __align__(16) __nv_bfloat16 g_Xl[(size_t)B_*T_*D_];
__device__ __align__(16) __nv_bfloat16 g_Ah[(size_t)B_*T_*D_];
__device__ __align__(16) __nv_bfloat16 g_Al[(size_t)B_*T_*D_];
__device__ __align__(16) __nv_bfloat16 g_Wqh[(size_t)3*D_*D_];
__device__ __align__(16) __nv_bfloat16 g_Wql[(size_t)3*D_*D_];
__device__ __align__(16) __nv_bfloat16 g_Woh[(size_t)D_*D_];
__device__ __align__(16) __nv_bfloat16 g_Wol[(size_t)D_*D_];

// ---------------- helpers ----------------
__device__ __forceinline__ uint32_t smem_u32(const void* p) {
    uint32_t a;
    asm("{ .reg .u64 t; cvta.to.shared.u64 t, %1; cvt.u32.u64 %0, t; }" : "=r"(a) : "l"(p));
    return a;
}
#define SWZ128(o) ((o) ^ (((o) >> 3) & 0x70))

#define LDMX4(r0, r1, r2, r3, addr)                                           \
    asm volatile("ldmatrix.sync.aligned.m8n8.x4.shared.b16 {%0,%1,%2,%3}, [%4];" \
                 : "=r"(r0), "=r"(r1), "=r"(r2), "=r"(r3) : "r"(addr))
#define LDMX4T(r0, r1, r2, r3, addr)                                          \
    asm volatile("ldmatrix.sync.aligned.m8n8.x4.trans.shared.b16 {%0,%1,%2,%3}, [%4];" \
                 : "=r"(r0), "=r"(r1), "=r"(r2), "=r"(r3) : "r"(addr))

#define MMA16816(d, a, b0v, b1v)                                              \
    asm volatile("mma.sync.aligned.m16n8k16.row.col.f32.bf16.bf16.f32 "       \
                 "{%0,%1,%2,%3}, {%4,%5,%6,%7}, {%8,%9}, {%0,%1,%2,%3};"      \
                 : "+f"((d)[0]), "+f"((d)[1]), "+f"((d)[2]), "+f"((d)[3])     \
                 : "r"((a)[0]), "r"((a)[1]), "r"((a)[2]), "r"((a)[3]),        \
                   "r"(b0v), "r"(b1v))

#define CP16(dst, src)                                                        \
    asm volatile("cp.async.cg.shared.global [%0], [%1], 16;" :: "r"(dst), "l"(src))
#define CP_COMMIT() asm volatile("cp.async.commit_group;" ::: "memory")
#define CP_WAIT(n)  asm volatile("cp.async.wait_group %0;" :: "n"(n) : "memory")

__device__ __forceinline__ uint32_t pack_bf16(float a, float b) {
    __nv_bfloat162 h = __floats2bfloat162_rn(a, b);
    return *(uint32_t*)&h;
}

// ---------------- prep: fp32 -> bf16 hi/lo split ----------------
__global__ __launch_bounds__(256) void split_bf16(const float* __restrict__ in,
                                                  __nv_bfloat16* __restrict__ hi,
                                                  __nv_bfloat16* __restrict__ lo, int n4) {
    int i = blockIdx.x * 256 + threadIdx.x;
    if (i >= n4) return;
    float4 v = ((const float4*)in)[i];
    union { __nv_bfloat16 b[4]; uint2 u; } H, L;
    const float* f = &v.x;
#pragma unroll
    for (int k = 0; k < 4; k++) {
        __nv_bfloat16 h = __float2bfloat16(f[k]);
        H.b[k] = h;
        L.b[k] = __float2bfloat16(f[k] - __bfloat162float(h));
    }
    ((uint2*)hi)[i] = H.u;
    ((uint2*)lo)[i] = L.u;
}

// ---------------- prep: W[K,N] -> Wt[N,K] bf16 hi/lo ----------------
__global__ __launch_bounds__(256) void transpose_split(const float* __restrict__ W,
                                                       __nv_bfloat16* __restrict__ Th,
                                                       __nv_bfloat16* __restrict__ Tl, int N) {
    __shared__ float tile[32][33];
    const int n0 = blockIdx.x * 32, k0 = blockIdx.y * 32;
    const int tx = threadIdx.x, ty = threadIdx.y;
#pragma unroll
    for (int i = 0; i < 4; i++)
        tile[ty + 8 * i][tx] = W[(size_t)(k0 + ty + 8 * i) * N + n0 + tx];
    __syncthreads();
#pragma unroll
    for (int i = 0; i < 4; i++) {
        float v = tile[tx][ty + 8 * i];
        __nv_bfloat16 h = __float2bfloat16(v);
        size_t o = (size_t)(n0 + ty + 8 * i) * GK + k0 + tx;
        Th[o] = h;
        Tl[o] = __float2bfloat16(v - __bfloat162float(h));
    }
}

// ---------------- 3-stage pipelined mma GEMM ----------
#define TILE_B 16384
#define STG_B  65536   // 4 tiles per stage
#define GSM_TOT (3 * STG_B)   // 192 KB
__global__ __launch_bounds__(256) void gemm_mma(
    const __nv_bfloat16* __restrict__ Ah, const __nv_bfloat16* __restrict__ Al,
    const __nv_bfloat16* __restrict__ Bh, const __nv_bfloat16* __restrict__ Bl,
    const float* __restrict__ bias, float* __restrict__ Cf,
    __nv_bfloat16* __restrict__ oQh, __nv_bfloat16* __restrict__ oQl,
    __nv_bfloat16* __restrict__ oKh, __nv_bfloat16* __restrict__ oKl,
    __nv_bfloat16* __restrict__ oVh, __nv_bfloat16* __restrict__ oVl,
    int N, int mode)
{
    extern __shared__ char smem[];
    const uint32_t sb = smem_u32(smem);
    const int tid = threadIdx.x, lane = tid & 31, wid = tid >> 5;
    const int wm = (wid & 1) * 64, wn = (wid >> 1) * 32;
    const int m0 = blockIdx.y * 128, n0 = blockIdx.x * 128;

    float acc[4][4][4];
#pragma unroll
    for (int i = 0; i < 4; i++)
#pragma unroll
        for (int j = 0; j < 4; j++)
#pragma unroll
            for (int k = 0; k < 4; k++) acc[i][j][k] = 0.f;

    const int lr = tid >> 3, lseg = tid & 7;
    const int a_row = wm + (lane & 15), a_k16 = lane >> 4;
    const int b_row = wn + (lane & 7) + ((lane & 16) >> 1), b_k16 = (lane >> 3) & 1;

    auto issue = [&](int c, int st) {
        const int kb = c * 64;
        const uint32_t stb = sb + st * STG_B;
#pragma unroll
        for (int it = 0; it < 4; it++) {
            const int r = lr + 32 * it;
            const size_t goA = (size_t)(m0 + r) * GK + kb + lseg * 8;
            const size_t goB = (size_t)(n0 + r) * GK + kb + lseg * 8;
            const uint32_t so = SWZ128((uint32_t)(r * 128 + lseg * 16));
            CP16(stb + so, Ah + goA);
            CP16(stb + TILE_B + so, Al + goA);
            CP16(stb + 2 * TILE_B + so, Bh + goB);
            CP16(stb + 3 * TILE_B + so, Bl + goB);
        }
        CP_COMMIT();
    };

    issue(0, 0);
    issue(1, 1);
    for (int c = 0; c < 16; c++) {
        if (c + 2 < 16) { issue(c + 2, (c + 2) % 3); CP_WAIT(2); }
        else if (c + 1 < 16) { CP_WAIT(1); }
        else { CP_WAIT(0); }
        __syncthreads();
        const uint32_t stb = sb + (c % 3) * STG_B;
        const uint32_t sAh = stb, sAl = stb + TILE_B,
                       sBh = stb + 2 * TILE_B, sBl = stb + 3 * TILE_B;
#pragma unroll
        for (int kk = 0; kk < 4; kk++) {
            const uint32_t akoff = kk * 32 + a_k16 * 16;
            const uint32_t bkoff = kk * 32 + b_k16 * 16;
            uint32_t ah[4][4], al[4][4], bh[2][4], bl[2][4];
#pragma unroll
            for (int mi = 0; mi < 4; mi++) {
                const uint32_t off = SWZ128((uint32_t)((a_row + mi * 16) * 128) + akoff);
                LDMX4(ah[mi][0], ah[mi][1], ah[mi][2], ah[mi][3], sAh + off);
                LDMX4(al[mi][0], al[mi][1], al[mi][2], al[mi][3], sAl + off);
            }
#pragma unroll
            for (int nj = 0; nj < 2; nj++) {
                const uint32_t off = SWZ128((uint32_t)((b_row + nj * 16) * 128) + bkoff);
                LDMX4(bh[nj][0], bh[nj][1], bh[nj][2], bh[nj][3], sBh + off);
                LDMX4(bl[nj][0], bl[nj][1], bl[nj][2], bl[nj][3], sBl + off);
            }
#pragma unroll
            for (int mi = 0; mi < 4; mi++)
#pragma unroll
                for (int nj = 0; nj < 2; nj++)
#pragma unroll
                    for (int q = 0; q < 2; q++) {
                        float* d = acc[mi][nj * 2 + q];
                        MMA16816(d, ah[mi], bh[nj][q * 2], bh[nj][q * 2 + 1]);
                        MMA16816(d, al[mi], bh[nj][q * 2], bh[nj][q * 2 + 1]);
                        MMA16816(d, ah[mi], bl[nj][q * 2], bl[nj][q * 2 + 1]);
                    }
        }
        __syncthreads();
    }

    // epilogue
    const int rl = lane >> 2, cl = (lane & 3) * 2;
#pragma unroll
    for (int mi = 0; mi < 4; mi++) {
        const int r_base = wm + mi * 16 + rl;
#pragma unroll
        for (int ni = 0; ni < 4; ni++) {
            const int cn = wn + ni * 8 + cl;
            const float2 b2 = *(const float2*)&bias[n0 + cn];
#pragma unroll
            for (int half = 0; half < 2; half++) {
                const int m = m0 + r_base + half * 8;
                float v0 = acc[mi][ni][half * 2 + 0] + b2.x;
                float v1 = acc[mi][ni][half * 2 + 1] + b2.y;
                if (mode == 0) {
                    float2 v; v.x = v0; v.y = v1;
                    *(float2*)&Cf[(size_t)m * N + n0 + cn] = v;
                } else {
                    const int b = m >> 11, t = m & 2047;
                    const int part = n0 >> 10;
                    const int d = (n0 & 1023) + cn;
                    const int h = d >> 6, dk = d & 63;
                    __nv_bfloat16 h0 = __float2bfloat16(v0);
                    __nv_bfloat16 h1 = __float2bfloat16(v1);
                    uint32_t hp;
                    { __nv_bfloat162 t2v; t2v.x = h0; t2v.y = h1; hp = *(uint32_t*)&t2v; }
                    uint32_t lw = pack_bf16(v0 - __bfloat162float(h0),
                                            v1 - __bfloat162float(h1));
                    const size_t off = (((size_t)(b * H_ + h)) * T_ + t) * DK_ + dk;
                    __nv_bfloat16 *dh, *dl;
                    if (part == 0)      { dh = oQh; dl = oQl; }
                    else if (part == 1) { dh = oKh; dl = oKl; }
                    else                { dh = oVh; dl = oVl; }
                    *(uint32_t*)(dh + off) = hp;
                    *(uint32_t*)(dl + off) = lw;
                }
            }
        }
    }
}

// ---------------- mma.sync flash attention (causal), cp.async 2-stage KV ----
// smem: Q hi/lo 32KB @0; KV stages @32KB: each 64KB (Kh,Kl,Vh,Vl) x2 = 160KB
#define ASM_QH 0
#define ASM_QL 16384
#define ASM_KV 32768
#define AKV_KH 0
#define AKV_KL 16384
#define AKV_VH 32768
#define AKV_VL 49152
#define ASM_TOT (32768 + 2 * 65536)

__global__ __launch_bounds__(256, 1) void attn_mma(
    const __nv_bfloat16* __restrict__ Qh, const __nv_bfloat16* __restrict__ Ql,
    const __nv_bfloat16* __restrict__ Kh, const __nv_bfloat16* __restrict__ Kl,
    const __nv_bfloat16* __restrict__ Vh, const __nv_bfloat16* __restrict__ Vl,
    __nv_bfloat16* __restrict__ Ah, __nv_bfloat16* __restrict__ Al)
{
    extern __shared__ char smem[];
    const uint32_t sb = smem_u32(smem);
    const int tid = threadIdx.x, lane = tid & 31, wid = tid >> 5;
    const int qt = gridDim.x - 1 - blockIdx.x;   // heavy tiles first
    const int q0 = qt * 128;
    const int h = blockIdx.y, b = blockIdx.z;
    const size_t hb = ((size_t)(b * H_ + h)) * T_ * DK_;
    const int lr = tid >> 1, lseg = tid & 1;     // 128 rows x 2 segs for Q (2 tiles)

    // Q tile hi/lo via cp.async (group 0)
    {
#pragma unroll
        for (int it = 0; it < 4; it++) {
            const int u = tid + 256 * it;
            const int r = u >> 3, seg = u & 7;
            const uint32_t so = SWZ128((uint32_t)(r * 128 + seg * 16));
            const size_t g = hb + (size_t)(q0 + r) * DK_ + seg * 8;
            CP16(sb + ASM_QH + so, Qh + g);
            CP16(sb + ASM_QL + so, Ql + g);
        }
        CP_COMMIT();
    }

    auto issueKV = [&](int kt, int st) {
        const int k0 = kt * 128;
        const uint32_t stb = sb + ASM_KV + st * 65536;
#pragma unroll
        for (int it = 0; it < 4; it++) {
            const int u = tid + 256 * it;
            const int r = u >> 3, seg = u & 7;
            const uint32_t so = SWZ128((uint32_t)(r * 128 + seg * 16));
            const size_t g = hb + (size_t)(k0 + r) * DK_ + seg * 8;
            CP16(stb + AKV_KH + so, Kh + g);
            CP16(stb + AKV_KL + so, Kl + g);
            CP16(stb + AKV_VH + so, Vh + g);
            CP16(stb + AKV_VL + so, Vl + g);
        }
        CP_COMMIT();
    };

    const int nkt = qt;                 // key tiles 0..qt
    issueKV(0, 0);
    CP_WAIT(1);                         // Q ready
    __syncthreads();

    // Q fragments (persistent)
    const int a_row = wid * 16 + (lane & 15), a_k16 = lane >> 4;
    uint32_t qfh[4][4], qfl[4][4];
#pragma unroll
    for (int kk = 0; kk < 4; kk++) {
        const uint32_t off = SWZ128((uint32_t)(a_row * 128 + kk * 32 + a_k16 * 16));
        LDMX4(qfh[kk][0], qfh[kk][1], qfh[kk][2], qfh[kk][3], sb + ASM_QH + off);
        LDMX4(qfl[kk][0], qfl[kk][1], qfl[kk][2], qfl[kk][3], sb + ASM_QL + off);
    }

    const int b_row = (lane & 7) + ((lane & 16) >> 1), b_k16 = (lane >> 3) & 1;
    const int vm = lane >> 3, vr = lane & 7;
    const int rr = lane >> 2, t2 = (lane & 3) * 2;

    float o[8][4];
#pragma unroll
    for (int i = 0; i < 8; i++)
#pragma unroll
        for (int j = 0; j < 4; j++) o[i][j] = 0.f;
    float m_r = -1e30f, m_r8 = -1e30f, l_r = 0.f, l_r8 = 0.f;

    for (int kt = 0; kt <= nkt; kt++) {
        if (kt + 1 <= nkt) { issueKV(kt + 1, (kt + 1) & 1); CP_WAIT(1); }
        else               { CP_WAIT(0); }
        __syncthreads();
        const uint32_t stb = sb + ASM_KV + (kt & 1) * 65536;
        const int k0 = kt * 128;

        // S = Q @ K^T (3-term)
        float s[16][4];
#pragma unroll
        for (int i = 0; i < 16; i++)
#pragma unroll
            for (int j = 0; j < 4; j++) s[i][j] = 0.f;
#pragma unroll
        for (int kk = 0; kk < 4; kk++) {
#pragma unroll
            for (int nn = 0; nn < 8; nn++) {
                const uint32_t off = SWZ128((uint32_t)((nn * 16 + b_row) * 128 + kk * 32 + b_k16 * 16));
                uint32_t kh[4], kl[4];
                LDMX4(kh[0], kh[1], kh[2], kh[3], stb + AKV_KH + off);
                LDMX4(kl[0], kl[1], kl[2], kl[3], stb + AKV_KL + off);
                float* s0 = s[2 * nn];
                float* s1 = s[2 * nn + 1];
                MMA16816(s0, qfh[kk], kh[0], kh[1]);
                MMA16816(s0, qfl[kk], kh[0], kh[1]);
                MMA16816(s0, qfh[kk], kl[0], kl[1]);
                MMA16816(s1, qfh[kk], kh[2], kh[3]);
                MMA16816(s1, qfl[kk], kh[2], kh[3]);
                MMA16816(s1, qfh[kk], kl[2], kl[3]);
            }
        }

        // scale + causal mask (only diagonal tile)
        const bool diag = (k0 == q0);
        const int qi_r = q0 + wid * 16 + rr;
#pragma unroll
        for (int ni = 0; ni < 16; ni++) {
            const int kc = k0 + ni * 8 + t2;
#pragma unroll
            for (int e = 0; e < 4; e++) {
                float v = s[ni][e] * 0.125f;
                if (diag) {
                    const int kj = kc + (e & 1);
                    const int qi = qi_r + ((e >> 1) << 3);
                    if (kj > qi) v = -1e30f;
                }
                s[ni][e] = v;
            }
        }

        // row max
        float rmr = -1e30f, rm8 = -1e30f;
#pragma unroll
        for (int ni = 0; ni < 16; ni++) {
            rmr = fmaxf(rmr, fmaxf(s[ni][0], s[ni][1]));
            rm8 = fmaxf(rm8, fmaxf(s[ni][2], s[ni][3]));
        }
        rmr = fmaxf(rmr, __shfl_xor_sync(0xffffffffu, rmr, 1));
        rmr = fmaxf(rmr, __shfl_xor_sync(0xffffffffu, rmr, 2));
        rm8 = fmaxf(rm8, __shfl_xor_sync(0xffffffffu, rm8, 1));
        rm8 = fmaxf(rm8, __shfl_xor_sync(0xffffffffu, rm8, 2));

        const float mnr = fmaxf(m_r, rmr), mn8 = fmaxf(m_r8, rm8);
        const float ar = __expf(m_r - mnr), a8 = __expf(m_r8 - mn8);
        m_r = mnr; m_r8 = mn8;
        l_r *= ar; l_r8 *= a8;
#pragma unroll
        for (int dn = 0; dn < 8; dn++) {
            o[dn][0] *= ar; o[dn][1] *= ar; o[dn][2] *= a8; o[dn][3] *= a8;
        }

        // P = exp(S-m) packed hi/lo; O += P@V (3-term)
#pragma unroll
        for (int kk = 0; kk < 8; kk++) {
            float p0 = __expf(s[2 * kk][0] - m_r);
            float p1 = __expf(s[2 * kk][1] - m_r);
            float p2 = __expf(s[2 * kk][2] - m_r8);
            float p3 = __expf(s[2 * kk][3] - m_r8);
            float p4 = __expf(s[2 * kk + 1][0] - m_r);
            float p5 = __expf(s[2 * kk + 1][1] - m_r);
            float p6 = __expf(s[2 * kk + 1][2] - m_r8);
            float p7 = __expf(s[2 * kk + 1][3] - m_r8);
            l_r  += p0 + p1 + p4 + p5;
            l_r8 += p2 + p3 + p6 + p7;

            uint32_t pH[4], pL[4];
            {
                __nv_bfloat16 h0 = __float2bfloat16(p0), h1 = __float2bfloat16(p1);
                __nv_bfloat16 h2 = __float2bfloat16(p2), h3 = __float2bfloat16(p3);
                __nv_bfloat16 h4 = __float2bfloat16(p4), h5 = __float2bfloat16(p5);
                __nv_bfloat16 h6 = __float2bfloat16(p6), h7 = __float2bfloat16(p7);
                __nv_bfloat162 w;
                w.x = h0; w.y = h1; pH[0] = *(uint32_t*)&w;
                w.x = h2; w.y = h3; pH[1] = *(uint32_t*)&w;
                w.x = h4; w.y = h5; pH[2] = *(uint32_t*)&w;
                w.x = h6; w.y = h7; pH[3] = *(uint32_t*)&w;
                pL[0] = pack_bf16(p0 - __bfloat162float(h0), p1 - __bfloat162float(h1));
                pL[1] = pack_bf16(p2 - __bfloat162float(h2), p3 - __bfloat162float(h3));
                pL[2] = pack_bf16(p4 - __bfloat162float(h4), p5 - __bfloat162float(h5));
                pL[3] = pack_bf16(p6 - __bfloat162float(h6), p7 - __bfloat162float(h7));
            }
#pragma unroll
            for (int dp = 0; dp < 4; dp++) {
                const uint32_t off = SWZ128((uint32_t)(
                    (kk * 16 + (vm & 1) * 8 + vr) * 128 + (vm >> 1) * 16 + dp * 32));
                uint32_t vh[4], vl[4];
                LDMX4T(vh[0], vh[1], vh[2], vh[3], stb + AKV_VH + off);
                LDMX4T(vl[0], vl[1], vl[2], vl[3], stb + AKV_VL + off);
                float* o0 = o[2 * dp];
                float* o1 = o[2 * dp + 1];
                MMA16816(o0, pH, vh[0], vh[1]);
                MMA16816(o0, pL, vh[0], vh[1]);
                MMA16816(o0, pH, vl[0], vl[1]);
                MMA16816(o1, pH, vh[2], vh[3]);
                MMA16816(o1, pL, vh[2], vh[3]);
                MMA16816(o1, pH, vl[2], vl[3]);
            }
        }
        __syncthreads();
    }

    // epilogue
    l_r  += __shfl_xor_sync(0xffffffffu, l_r, 1);
    l_r  += __shfl_xor_sync(0xffffffffu, l_r, 2);
    l_r8 += __shfl_xor_sync(0xffffffffu, l_r8, 1);
    l_r8 += __shfl_xor_sync(0xffffffffu, l_r8, 2);
    const float ir = 1.f / l_r, i8 = 1.f / l_r8;
    const int trow = q0 + wid * 16 + rr;
#pragma unroll
    for (int dn = 0; dn < 8; dn++) {
        float v0 = o[dn][0] * ir, v1 = o[dn][1] * ir;
        float v2 = o[dn][2] * i8, v3 = o[dn][3] * i8;
        const int col = h * DK_ + dn * 8 + t2;
        __nv_bfloat16 h0 = __float2bfloat16(v0), h1 = __float2bfloat16(v1);
        __nv_bfloat16 h2 = __float2bfloat16(v2), h3 = __float2bfloat16(v3);
        __nv_bfloat162 w;
        size_t o1 = ((size_t)(b * T_ + trow)) * D_ + col;
        size_t o2 = ((size_t)(b * T_ + trow + 8)) * D_ + col;
        w.x = h0; w.y = h1; *(uint32_t*)(Ah + o1) = *(uint32_t*)&w;
        w.x = h2; w.y = h3; *(uint32_t*)(Ah + o2) = *(uint32_t*)&w;
        *(uint32_t*)(Al + o1) = pack_bf16(v0 - __bfloat162float(h0), v1 - __bfloat162float(h1));
        *(uint32_t*)(Al + o2) = pack_bf16(v2 - __bfloat162float(h2), v3 - __bfloat162float(h3));
    }
}

// ---------------------------------------------------------------------------
extern "C" void kernel_launch(void* const* d_in, const int* in_sizes, int n_in,
                              void* d_out, int out_size)
{
    const float* x     = (const float*)d_in[0];
    const float* W_qkv = (const float*)d_in[1];
    const float* b_qkv = (const float*)d_in[2];
    const float* W_o   = (const float*)d_in[3];
    const float* b_o   = (const float*)d_in[4];

    __nv_bfloat16 *Qh, *Ql, *Kh, *Kl, *Vh, *Vl, *Xh, *Xl, *Ahp, *Alp, *Wqh, *Wql, *Woh, *Wol;
    cudaGetSymbolAddress((void**)&Qh, g_Qh); cudaGetSymbolAddress((void**)&Ql, g_Ql);
    cudaGetSymbolAddress((void**)&Kh, g_Kh); cudaGetSymbolAddress((void**)&Kl, g_Kl);
    cudaGetSymbolAddress((void**)&Vh, g_Vh); cudaGetSymbolAddress((void**)&Vl, g_Vl);
    cudaGetSymbolAddress((void**)&Xh, g_Xh); cudaGetSymbolAddress((void**)&Xl, g_Xl);
    cudaGetSymbolAddress((void**)&Ahp, g_Ah); cudaGetSymbolAddress((void**)&Alp, g_Al);
    cudaGetSymbolAddress((void**)&Wqh, g_Wqh); cudaGetSymbolAddress((void**)&Wql, g_Wql);
    cudaGetSymbolAddress((void**)&Woh, g_Woh); cudaGetSymbolAddress((void**)&Wol, g_Wol);

    const int M = B_ * T_;
    const int n4 = M * D_ / 4;

    split_bf16<<<(n4 + 255) / 256, 256>>>(x, Xh, Xl, n4);
    {
        dim3 g(3 * D_ / 32, D_ / 32), blk(32, 8);
        transpose_split<<<g, blk>>>(W_qkv, Wqh, Wql, 3 * D_);
    }
    {
        dim3 g(D_ / 32, D_ / 32), blk(32, 8);
        transpose_split<<<g, blk>>>(W_o, Woh, Wol, D_);
    }

    cudaFuncSetAttribute(gemm_mma, cudaFuncAttributeMaxDynamicSharedMemorySize, GSM_TOT);
    cudaFuncSetAttribute(attn_mma, cudaFuncAttributeMaxDynamicSharedMemorySize, ASM_TOT);

    // 1) QKV projection -> bf16 hi/lo head-major Q/K/V
    {
        dim3 grid(3 * D_ / 128, M / 128);
        gemm_mma<<<grid, 256, GSM_TOT>>>(Xh, Xl, Wqh, Wql, b_qkv, nullptr,
                                         Qh, Ql, Kh, Kl, Vh, Vl, 3 * D_, 1);
    }

    // 2) causal flash attention (tensor cores) -> Ah/Al bf16 hi/lo
    {
        dim3 grid(T_ / 128, H_, B_);
        attn_mma<<<grid, 256, ASM_TOT>>>(Qh, Ql, Kh, Kl, Vh, Vl, Ahp, Alp);
    }

    // 3) output projection -> fp32 d_out
    {
        dim3 grid(D_ / 128, M / 128);
        gemm_mma<<<grid, 256, GSM_TOT>>>(Ahp, Alp, Woh, Wol, b_o, (float*)d_out,
                                         nullptr, nullptr, nullptr, nullptr, nullptr, nullptr,
                                         D_, 0);
    }
}